// round 12
// baseline (speedup 1.0000x reference)
#include <cuda_runtime.h>
#include <stdint.h>

#define BATCH 4096
#define IN_F  2048
#define OUT_F 4096
#define WORDS (IN_F / 64)     // 32 u64 per row (one per lane)
#define HT_SIZE 8192          // 32 KB smem; 4096 entries -> 50% load
#define MROWS 32              // batch rows per match block

// Scratch (allocation-free: __device__ globals)
__device__ uint64_t g_xbits[(size_t)BATCH * WORDS];
__device__ uint64_t g_pbits[(size_t)OUT_F * WORDS];
__device__ uint64_t g_xsig[BATCH];
__device__ uint64_t g_psig[OUT_F];

__device__ __forceinline__ uint32_t hash_sig(uint64_t s)
{
    s ^= s >> 33; s *= 0xff51afd7ed558ccdULL; s ^= s >> 33;
    return (uint32_t)s & (HT_SIZE - 1);
}

// -----------------------------------------------------------------------------
// Kernel 1: ballot-free pack + zero-fill.
//   1024 blocks x 256 threads; one warp per row (first 4096 = x, rest = path).
//   Thread `lane` packs elements {it*128 + lane*4 + j} bit j+4*it of ITS OWN
//   u64 word — a fixed permutation of element order, identical for x and path
//   rows, so packed-row equality <=> original-bit-row equality (exact).
//   No ballots, no lane-conditional selects; coalesced 8B stores.
//   Row sig = XOR-reduce of lane-salted mixes of the 32 words (5 shfl_xor).
// -----------------------------------------------------------------------------
__global__ __launch_bounds__(256) void fsu_pack_zero_kernel(
    const float* __restrict__ x,
    const float* __restrict__ w,
    const float* __restrict__ rng,
    float4* __restrict__ outv)
{
    // ---- zero-fill slice (pure store stream, overlaps pack loads) ----
    {
        const float4 z = make_float4(0.0f, 0.0f, 0.0f, 0.0f);
        const int base = blockIdx.x * 4096;          // 4M float4 / 1024 blocks
        #pragma unroll
        for (int k = 0; k < 16; ++k)
            outv[base + k * 256 + threadIdx.x] = z;
    }

    const int gwarp = (blockIdx.x * blockDim.x + threadIdx.x) >> 5;
    const int lane  = threadIdx.x & 31;
    const bool isX  = gwarp < BATCH;
    const int row   = isX ? gwarp : (gwarp - BATCH);

    const float rv = __ldg(rng);
    const float4* src = reinterpret_cast<const float4*>(
        (isX ? (x + (size_t)row * IN_F) : (w + (size_t)row * IN_F)));

    uint32_t lo = 0, hi = 0;

    #pragma unroll
    for (int it = 0; it < 16; ++it) {
        const float4 v = __ldg(src + it * 32 + lane);
        uint32_t b0, b1, b2, b3;
        if (isX) {
            b0 = (v.x > 0.5f); b1 = (v.y > 0.5f);
            b2 = (v.z > 0.5f); b3 = (v.w > 0.5f);
        } else {
            // BinGen/BSGen: prob=(w+1)*0.5; source=round(prob*256); bit = source > rng
            // round = rintf (half-to-even) matches jnp.round exactly.
            b0 = (rintf((v.x + 1.0f) * 0.5f * 256.0f) > rv);
            b1 = (rintf((v.y + 1.0f) * 0.5f * 256.0f) > rv);
            b2 = (rintf((v.z + 1.0f) * 0.5f * 256.0f) > rv);
            b3 = (rintf((v.w + 1.0f) * 0.5f * 256.0f) > rv);
        }
        const uint32_t nib = b0 | (b1 << 1) | (b2 << 2) | (b3 << 3);
        if (it < 8) lo |= nib << (4 * it);
        else        hi |= nib << (4 * (it - 8));
    }

    const uint64_t myword = (uint64_t)lo | ((uint64_t)hi << 32);

    // lane-salted mix, then XOR butterfly reduction -> row signature
    uint64_t s = myword ^ (0x9E3779B97F4A7C15ull * (uint64_t)(lane + 1));
    s *= 0xff51afd7ed558ccdULL;
    s ^= s >> 31;
    #pragma unroll
    for (int off = 16; off > 0; off >>= 1)
        s ^= __shfl_xor_sync(0xFFFFFFFFu, s, off);

    if (isX) {
        g_xbits[(size_t)row * WORDS + lane] = myword;
        if (lane == 0) g_xsig[row] = s;
    } else {
        g_pbits[(size_t)row * WORDS + lane] = myword;
        if (lane == 0) g_psig[row] = s;
    }
}

// Exact verification: full 2048-bit compare. Equal sigs alone is never
// trusted — collisions cannot produce wrong output.
__device__ __noinline__ bool fsu_full_cmp(int b, int o)
{
    const uint64_t* xb = &g_xbits[(size_t)b * WORDS];
    const uint64_t* pb = &g_pbits[(size_t)o * WORDS];
    #pragma unroll 8
    for (int k = 0; k < WORDS; ++k)
        if (__ldg(xb + k) != __ldg(pb + k)) return false;
    return true;
}

// -----------------------------------------------------------------------------
// Kernel 2: hash-based match. 128 blocks x 256 threads. Each block builds a
// smem hash table of all 4096 psigs (16 independent CAS/thread), then probes
// its 32 batch rows (one thread per row): 4096 probes total instead of 16M
// brute-force compares. out[] is already zeroed by kernel 1 (stream order);
// verified matches (expected: none) written directly.
// -----------------------------------------------------------------------------
__global__ __launch_bounds__(256) void fsu_match_kernel(float* __restrict__ out)
{
    __shared__ uint32_t s_ht[HT_SIZE];               // 32 KB

    const int tid = threadIdx.x;

    #pragma unroll
    for (int i = tid; i < HT_SIZE; i += 256)
        s_ht[i] = 0;
    __syncthreads();

    // insert all psigs (stores o+1); coalesced reads, smem CAS
    #pragma unroll
    for (int k = 0; k < OUT_F / 256; ++k) {          // 16 inserts per thread
        const int o = k * 256 + tid;
        uint32_t h = hash_sig(__ldg(&g_psig[o]));
        while (atomicCAS(&s_ht[h], 0u, (uint32_t)(o + 1)) != 0u)
            h = (h + 1) & (HT_SIZE - 1);
    }
    __syncthreads();

    // probe: one thread per batch row (32 rows per block)
    if (tid < MROWS) {
        const int b = blockIdx.x * MROWS + tid;
        const uint64_t xs = __ldg(&g_xsig[b]);
        uint32_t h = hash_sig(xs);
        uint32_t e;
        while ((e = s_ht[h]) != 0u) {
            const int o = (int)e - 1;
            if (__ldg(&g_psig[o]) == xs && fsu_full_cmp(b, o))
                out[(size_t)b * OUT_F + o] = 1.0f;
            h = (h + 1) & (HT_SIZE - 1);
        }
    }
}

extern "C" void kernel_launch(void* const* d_in, const int* in_sizes, int n_in,
                              void* d_out, int out_size)
{
    const float* x   = (const float*)d_in[0];
    const float* w   = (const float*)d_in[1];
    const float* rng = (const float*)d_in[2];
    float* out = (float*)d_out;

    // (BATCH + OUT_F) warps = 8192 -> 1024 blocks of 8 warps; each block also
    // zero-fills 4096 float4 of the output.
    fsu_pack_zero_kernel<<<1024, 256>>>(x, w, rng,
                                        reinterpret_cast<float4*>(out));

    fsu_match_kernel<<<BATCH / MROWS, 256>>>(out);   // 128 blocks
}

// round 13
// speedup vs baseline: 1.9015x; 1.9015x over previous
#include <cuda_runtime.h>
#include <stdint.h>

#define BATCH 4096
#define IN_F  2048
#define OUT_F 4096
#define WORDS (IN_F / 64)     // 32 u64 per row
#define MROWS 32              // batch rows per match block

// Scratch (allocation-free: __device__ globals)
__device__ uint64_t g_xbits[(size_t)BATCH * WORDS];
__device__ uint64_t g_pbits[(size_t)OUT_F * WORDS];
__device__ uint32_t g_xsig[BATCH];
__device__ uint32_t g_psig[OUT_F];

// -----------------------------------------------------------------------------
// Kernel 1: fused pack + zero-fill (HBM-bound: 64 MB read + 64 MB write).
//   1024 blocks x 256 threads. Each block packs 8 rows (one warp per row)
//   AND zero-fills a 4096-float4 slice of the output.
//   Pack: float4 loads, 4 ballots/iter. Bit order within packed words is a
//   fixed permutation of element order, identical for x and path rows, so
//   packed-row equality <=> original-bit-row equality (exact).
//   Signature folded to 32 bits (match kernel is issue-bound; u32 halves it).
// -----------------------------------------------------------------------------
__global__ __launch_bounds__(256) void fsu_pack_zero_kernel(
    const float* __restrict__ x,
    const float* __restrict__ w,
    const float* __restrict__ rng,
    float4* __restrict__ outv)
{
    // ---- zero-fill slice (pure store stream, overlaps with pack loads) ----
    {
        const float4 z = make_float4(0.0f, 0.0f, 0.0f, 0.0f);
        const int base = blockIdx.x * 4096;          // 4M float4 / 1024 blocks
        #pragma unroll
        for (int k = 0; k < 16; ++k)
            outv[base + k * 256 + threadIdx.x] = z;
    }

    // ---- pack 8 rows (one warp per row) ----
    const int gwarp = (blockIdx.x * blockDim.x + threadIdx.x) >> 5;
    const int lane  = threadIdx.x & 31;
    const bool isX  = gwarp < BATCH;
    const int row   = isX ? gwarp : (gwarp - BATCH);

    const float rv = __ldg(rng);
    const float4* src = reinterpret_cast<const float4*>(
        (isX ? (x + (size_t)row * IN_F) : (w + (size_t)row * IN_F)));

    uint64_t sig = 0;
    uint64_t myword = 0;

    #pragma unroll
    for (int it = 0; it < IN_F / 128; ++it) {        // 16 iterations
        const float4 v = __ldg(src + it * 32 + lane);
        bool b0, b1, b2, b3;
        if (isX) {
            b0 = (v.x > 0.5f); b1 = (v.y > 0.5f);
            b2 = (v.z > 0.5f); b3 = (v.w > 0.5f);
        } else {
            // BinGen/BSGen: prob=(w+1)*0.5; source=round(prob*256); bit = source > rng
            b0 = (rintf((v.x + 1.0f) * 0.5f * 256.0f) > rv);
            b1 = (rintf((v.y + 1.0f) * 0.5f * 256.0f) > rv);
            b2 = (rintf((v.z + 1.0f) * 0.5f * 256.0f) > rv);
            b3 = (rintf((v.w + 1.0f) * 0.5f * 256.0f) > rv);
        }
        const uint32_t m0 = __ballot_sync(0xFFFFFFFFu, b0);
        const uint32_t m1 = __ballot_sync(0xFFFFFFFFu, b1);
        const uint32_t m2 = __ballot_sync(0xFFFFFFFFu, b2);
        const uint32_t m3 = __ballot_sync(0xFFFFFFFFu, b3);
        const uint64_t wa = (uint64_t)m0 | ((uint64_t)m1 << 32);
        const uint64_t wb = (uint64_t)m2 | ((uint64_t)m3 << 32);
        if (lane == 2 * it)     myword = wa;
        if (lane == 2 * it + 1) myword = wb;
        sig = sig * 0x9E3779B97F4A7C15ull + wa;
        sig = sig * 0x9E3779B97F4A7C15ull + wb;
    }

    // fold to 32 bits (equal rows -> equal sig32; verification is exact anyway)
    sig *= 0xff51afd7ed558ccdULL;
    const uint32_t sig32 = (uint32_t)(sig ^ (sig >> 32));

    if (isX) {
        g_xbits[(size_t)row * WORDS + lane] = myword;
        if (lane == 0) g_xsig[row] = sig32;
    } else {
        g_pbits[(size_t)row * WORDS + lane] = myword;
        if (lane == 0) g_psig[row] = sig32;
    }
}

// Exact verification: full 2048-bit compare. Equal sigs alone is never
// trusted — collisions cannot produce wrong output.
__device__ __noinline__ bool fsu_full_cmp(int b, int o)
{
    const uint64_t* xb = &g_xbits[(size_t)b * WORDS];
    const uint64_t* pb = &g_pbits[(size_t)o * WORDS];
    #pragma unroll 8
    for (int k = 0; k < WORDS; ++k)
        if (__ldg(xb + k) != __ldg(pb + k)) return false;
    return true;
}

// -----------------------------------------------------------------------------
// Kernel 2: brute-force sig matrix compare (u32). 128 blocks x 1024 threads.
// Block owns MROWS=32 batch rows (sig32s in registers); each thread scans 4
// psigs -> 128 independent u32 register compares, no dependent chains.
// Runs after kernel 1 on the stream, so out[] is already zeroed; sig hits
// (expected ~0.004 chip-wide) are exactly verified before writing.
// -----------------------------------------------------------------------------
__global__ __launch_bounds__(1024) void fsu_match_kernel(float* __restrict__ out)
{
    __shared__ uint32_t s_xsig[MROWS];
    const int tid   = threadIdx.x;
    const int bbase = blockIdx.x * MROWS;

    if (tid < MROWS) s_xsig[tid] = __ldg(&g_xsig[bbase + tid]);
    __syncthreads();

    uint32_t xs[MROWS];
    #pragma unroll
    for (int r = 0; r < MROWS; ++r) xs[r] = s_xsig[r];

    #pragma unroll
    for (int k = 0; k < OUT_F / 1024; ++k) {         // 4 psigs per thread
        const int o = k * 1024 + tid;
        const uint32_t ps = __ldg(&g_psig[o]);
        #pragma unroll
        for (int r = 0; r < MROWS; ++r) {
            if (ps == xs[r]) {
                const int b = bbase + r;
                if (fsu_full_cmp(b, o))
                    out[(size_t)b * OUT_F + o] = 1.0f;
            }
        }
    }
}

extern "C" void kernel_launch(void* const* d_in, const int* in_sizes, int n_in,
                              void* d_out, int out_size)
{
    const float* x   = (const float*)d_in[0];
    const float* w   = (const float*)d_in[1];
    const float* rng = (const float*)d_in[2];
    float* out = (float*)d_out;

    // (BATCH + OUT_F) warps = 8192 -> 1024 blocks of 8 warps; each block also
    // zero-fills 4096 float4 of the output.
    fsu_pack_zero_kernel<<<1024, 256>>>(x, w, rng,
                                        reinterpret_cast<float4*>(out));

    fsu_match_kernel<<<BATCH / MROWS, 1024>>>(out);  // 128 blocks
}